// round 5
// baseline (speedup 1.0000x reference)
#include <cuda_runtime.h>
#include <cuda_bf16.h>

#define N_NODES 1000000

// 4 MB scratch for per-node exp-sums (static __device__ per allocation rules)
__device__ float g_rowsum[N_NODES];

__device__ __forceinline__ float et_of(float x) {
    // exp(leaky_relu(x, 0.01))
    float lr = x > 0.0f ? x : 0.01f * x;
    return __expf(lr);
}

__global__ void zero_rowsum_kernel() {
    int i = blockIdx.x * blockDim.x + threadIdx.x;
    if (i < N_NODES / 4) {
        reinterpret_cast<float4*>(g_rowsum)[i] = make_float4(0.f, 0.f, 0.f, 0.f);
    }
}

// 8 edges per thread. Streaming reads use evict-first (.cs) so the 4MB rowsum
// array stays L2-resident for the random atomics.
__global__ void accum_kernel(const int* __restrict__ row,
                             const float* __restrict__ attr,
                             int E) {
    long long i = (long long)(blockIdx.x * blockDim.x + threadIdx.x) * 8;
    if (i + 7 < E) {
        int4   r0 = __ldcs(reinterpret_cast<const int4*>(row + i));
        int4   r1 = __ldcs(reinterpret_cast<const int4*>(row + i + 4));
        float4 a0 = __ldcs(reinterpret_cast<const float4*>(attr + i));
        float4 a1 = __ldcs(reinterpret_cast<const float4*>(attr + i + 4));
        atomicAdd(&g_rowsum[r0.x], et_of(a0.x));
        atomicAdd(&g_rowsum[r0.y], et_of(a0.y));
        atomicAdd(&g_rowsum[r0.z], et_of(a0.z));
        atomicAdd(&g_rowsum[r0.w], et_of(a0.w));
        atomicAdd(&g_rowsum[r1.x], et_of(a1.x));
        atomicAdd(&g_rowsum[r1.y], et_of(a1.y));
        atomicAdd(&g_rowsum[r1.z], et_of(a1.z));
        atomicAdd(&g_rowsum[r1.w], et_of(a1.w));
    } else {
        for (; i < E; i++) {
            atomicAdd(&g_rowsum[row[i]], et_of(attr[i]));
        }
    }
}

__global__ void norm_kernel(const int* __restrict__ row,
                            const float* __restrict__ attr,
                            float* __restrict__ out,
                            int E) {
    long long i = (long long)(blockIdx.x * blockDim.x + threadIdx.x) * 8;
    if (i + 7 < E) {
        int4   r0 = __ldcs(reinterpret_cast<const int4*>(row + i));
        int4   r1 = __ldcs(reinterpret_cast<const int4*>(row + i + 4));
        float4 a0 = __ldcs(reinterpret_cast<const float4*>(attr + i));
        float4 a1 = __ldcs(reinterpret_cast<const float4*>(attr + i + 4));
        // rowsum gathers: default policy -> L2-resident hits
        float s0 = __ldg(&g_rowsum[r0.x]);
        float s1 = __ldg(&g_rowsum[r0.y]);
        float s2 = __ldg(&g_rowsum[r0.z]);
        float s3 = __ldg(&g_rowsum[r0.w]);
        float s4 = __ldg(&g_rowsum[r1.x]);
        float s5 = __ldg(&g_rowsum[r1.y]);
        float s6 = __ldg(&g_rowsum[r1.z]);
        float s7 = __ldg(&g_rowsum[r1.w]);
        float4 o0, o1;
        o0.x = __fdividef(et_of(a0.x), s0);
        o0.y = __fdividef(et_of(a0.y), s1);
        o0.z = __fdividef(et_of(a0.z), s2);
        o0.w = __fdividef(et_of(a0.w), s3);
        o1.x = __fdividef(et_of(a1.x), s4);
        o1.y = __fdividef(et_of(a1.y), s5);
        o1.z = __fdividef(et_of(a1.z), s6);
        o1.w = __fdividef(et_of(a1.w), s7);
        __stcs(reinterpret_cast<float4*>(out + i), o0);
        __stcs(reinterpret_cast<float4*>(out + i + 4), o1);
    } else {
        for (; i < E; i++) {
            out[i] = __fdividef(et_of(attr[i]), g_rowsum[row[i]]);
        }
    }
}

extern "C" void kernel_launch(void* const* d_in, const int* in_sizes, int n_in,
                              void* d_out, int out_size) {
    // metadata order: edge_index (int32, [2, E] row-major), edge_attr (f32, [E]), N
    const int*   edge_index = (const int*)d_in[0];
    const float* edge_attr  = (const float*)d_in[1];
    float*       out        = (float*)d_out;

    int E = in_sizes[1];           // edge_attr element count
    const int* row = edge_index;   // edge_index[0] = first E elements

    const int TPB = 256;
    int zero_blocks = (N_NODES / 4 + TPB - 1) / TPB;
    int edge_threads = (E + 7) / 8;
    int edge_blocks = (edge_threads + TPB - 1) / TPB;

    zero_rowsum_kernel<<<zero_blocks, TPB>>>();
    accum_kernel<<<edge_blocks, TPB>>>(row, edge_attr, E);
    norm_kernel<<<edge_blocks, TPB>>>(row, edge_attr, out, E);
}

// round 7
// speedup vs baseline: 1.0536x; 1.0536x over previous
#include <cuda_runtime.h>
#include <cuda_bf16.h>

#define N_NODES 1000000

// 4 MB scratch for per-node exp-sums (static __device__ per allocation rules)
__device__ float g_rowsum[N_NODES];

__device__ __forceinline__ float et_of(float x) {
    // exp(leaky_relu(x, 0.01))
    float lr = x > 0.0f ? x : 0.01f * x;
    return __expf(lr);
}

__global__ void zero_rowsum_kernel() {
    int i = blockIdx.x * blockDim.x + threadIdx.x;
    if (i < N_NODES / 4) {
        reinterpret_cast<float4*>(g_rowsum)[i] = make_float4(0.f, 0.f, 0.f, 0.f);
    }
}

__global__ void accum_kernel(const int* __restrict__ row,
                             const float* __restrict__ attr,
                             int E) {
    long long i = (long long)(blockIdx.x * blockDim.x + threadIdx.x) * 4;
    if (i + 3 < E) {
        int4   r = *reinterpret_cast<const int4*>(row + i);
        float4 a = *reinterpret_cast<const float4*>(attr + i);
        atomicAdd(&g_rowsum[r.x], et_of(a.x));
        atomicAdd(&g_rowsum[r.y], et_of(a.y));
        atomicAdd(&g_rowsum[r.z], et_of(a.z));
        atomicAdd(&g_rowsum[r.w], et_of(a.w));
    } else {
        for (; i < E; i++) {
            atomicAdd(&g_rowsum[row[i]], et_of(attr[i]));
        }
    }
}

// Convert sums to reciprocals once (1M coalesced ops) so the 33.5M-edge
// norm pass multiplies instead of divides.
__global__ void recip_kernel() {
    int i = blockIdx.x * blockDim.x + threadIdx.x;
    if (i < N_NODES / 4) {
        float4 s = reinterpret_cast<float4*>(g_rowsum)[i];
        float4 r;
        r.x = __frcp_rn(s.x);
        r.y = __frcp_rn(s.y);
        r.z = __frcp_rn(s.z);
        r.w = __frcp_rn(s.w);
        reinterpret_cast<float4*>(g_rowsum)[i] = r;
    }
}

__global__ void norm_kernel(const int* __restrict__ row,
                            const float* __restrict__ attr,
                            float* __restrict__ out,
                            int E) {
    long long i = (long long)(blockIdx.x * blockDim.x + threadIdx.x) * 4;
    if (i + 3 < E) {
        int4   r = *reinterpret_cast<const int4*>(row + i);
        float4 a = *reinterpret_cast<const float4*>(attr + i);
        // random 4B gathers: L2-only path (.cg) — no L1 allocation, so the
        // streaming row/attr lines keep L1
        float s0 = __ldcg(&g_rowsum[r.x]);
        float s1 = __ldcg(&g_rowsum[r.y]);
        float s2 = __ldcg(&g_rowsum[r.z]);
        float s3 = __ldcg(&g_rowsum[r.w]);
        float4 o;
        o.x = et_of(a.x) * s0;
        o.y = et_of(a.y) * s1;
        o.z = et_of(a.z) * s2;
        o.w = et_of(a.w) * s3;
        *reinterpret_cast<float4*>(out + i) = o;
    } else {
        for (; i < E; i++) {
            out[i] = et_of(attr[i]) * __ldcg(&g_rowsum[row[i]]);
        }
    }
}

extern "C" void kernel_launch(void* const* d_in, const int* in_sizes, int n_in,
                              void* d_out, int out_size) {
    // metadata order: edge_index (int32, [2, E] row-major), edge_attr (f32, [E]), N
    const int*   edge_index = (const int*)d_in[0];
    const float* edge_attr  = (const float*)d_in[1];
    float*       out        = (float*)d_out;

    int E = in_sizes[1];           // edge_attr element count
    const int* row = edge_index;   // edge_index[0] = first E elements

    const int TPB = 256;
    int node_blocks = (N_NODES / 4 + TPB - 1) / TPB;
    int edge_threads = (E + 3) / 4;
    int edge_blocks = (edge_threads + TPB - 1) / TPB;

    zero_rowsum_kernel<<<node_blocks, TPB>>>();
    accum_kernel<<<edge_blocks, TPB>>>(row, edge_attr, E);
    recip_kernel<<<node_blocks, TPB>>>();
    norm_kernel<<<edge_blocks, TPB>>>(row, edge_attr, out, E);
}

// round 11
// speedup vs baseline: 1.0566x; 1.0029x over previous
#include <cuda_runtime.h>
#include <cuda_bf16.h>

#define N_NODES 1000000

// 4 MB scratch for per-node exp-sums (static __device__ per allocation rules)
__device__ float g_rowsum[N_NODES];

__device__ __forceinline__ void pdl_trigger() {
    // allow the next kernel's CTAs to launch early (PDL)
    asm volatile("griddepcontrol.launch_dependents;");
}
__device__ __forceinline__ void pdl_wait() {
    // block until the previous grid's memory is flushed
    asm volatile("griddepcontrol.wait;" ::: "memory");
}

__device__ __forceinline__ float et_of(float x) {
    // exp(leaky_relu(x, 0.01)) ; leaky_relu(x) == max(x, 0.01x)
    float lr = fmaxf(x, 0.01f * x);
    return __expf(lr);
}

__global__ void zero_rowsum_kernel() {
    pdl_trigger();
    int i = blockIdx.x * blockDim.x + threadIdx.x;
    if (i < N_NODES / 4) {
        reinterpret_cast<float4*>(g_rowsum)[i] = make_float4(0.f, 0.f, 0.f, 0.f);
    }
}

__global__ void accum_kernel(const int* __restrict__ row,
                             const float* __restrict__ attr,
                             int E) {
    pdl_trigger();
    long long i = (long long)(blockIdx.x * blockDim.x + threadIdx.x) * 4;
    if (i + 3 < E) {
        // independent streaming loads issue BEFORE waiting on zero_rowsum
        int4   r = *reinterpret_cast<const int4*>(row + i);
        float4 a = *reinterpret_cast<const float4*>(attr + i);
        float e0 = et_of(a.x), e1 = et_of(a.y), e2 = et_of(a.z), e3 = et_of(a.w);
        pdl_wait();
        atomicAdd(&g_rowsum[r.x], e0);
        atomicAdd(&g_rowsum[r.y], e1);
        atomicAdd(&g_rowsum[r.z], e2);
        atomicAdd(&g_rowsum[r.w], e3);
    } else {
        pdl_wait();
        for (; i < E; i++) {
            atomicAdd(&g_rowsum[row[i]], et_of(attr[i]));
        }
    }
}

// Convert sums to reciprocals once (1M coalesced ops) so the 33.5M-edge
// norm pass multiplies instead of divides.
__global__ void recip_kernel() {
    pdl_trigger();
    pdl_wait();
    int i = blockIdx.x * blockDim.x + threadIdx.x;
    if (i < N_NODES / 4) {
        float4 s = reinterpret_cast<float4*>(g_rowsum)[i];
        float4 r;
        r.x = __frcp_rn(s.x);
        r.y = __frcp_rn(s.y);
        r.z = __frcp_rn(s.z);
        r.w = __frcp_rn(s.w);
        reinterpret_cast<float4*>(g_rowsum)[i] = r;
    }
}

__global__ void norm_kernel(const int* __restrict__ row,
                            const float* __restrict__ attr,
                            float* __restrict__ out,
                            int E) {
    long long i = (long long)(blockIdx.x * blockDim.x + threadIdx.x) * 4;
    if (i + 3 < E) {
        // streaming prologue overlaps recip_kernel's tail via PDL
        int4   r = *reinterpret_cast<const int4*>(row + i);
        float4 a = *reinterpret_cast<const float4*>(attr + i);
        float e0 = et_of(a.x), e1 = et_of(a.y), e2 = et_of(a.z), e3 = et_of(a.w);
        pdl_wait();
        float s0 = __ldg(&g_rowsum[r.x]);
        float s1 = __ldg(&g_rowsum[r.y]);
        float s2 = __ldg(&g_rowsum[r.z]);
        float s3 = __ldg(&g_rowsum[r.w]);
        float4 o;
        o.x = e0 * s0;
        o.y = e1 * s1;
        o.z = e2 * s2;
        o.w = e3 * s3;
        *reinterpret_cast<float4*>(out + i) = o;
    } else {
        pdl_wait();
        for (; i < E; i++) {
            out[i] = et_of(attr[i]) * __ldg(&g_rowsum[row[i]]);
        }
    }
}

extern "C" void kernel_launch(void* const* d_in, const int* in_sizes, int n_in,
                              void* d_out, int out_size) {
    // metadata order: edge_index (int32, [2, E] row-major), edge_attr (f32, [E]), N
    const int*   edge_index = (const int*)d_in[0];
    const float* edge_attr  = (const float*)d_in[1];
    float*       out        = (float*)d_out;

    int E = in_sizes[1];           // edge_attr element count
    const int* row = edge_index;   // edge_index[0] = first E elements

    const unsigned TPB = 256;
    unsigned node_blocks = (N_NODES / 4 + TPB - 1) / TPB;
    unsigned edge_threads = (unsigned)((E + 3) / 4);
    unsigned edge_blocks = (edge_threads + TPB - 1) / TPB;

    cudaLaunchAttribute pdl_attr[1];
    pdl_attr[0].id = cudaLaunchAttributeProgrammaticStreamSerialization;
    pdl_attr[0].val.programmaticStreamSerializationAllowed = 1;

    // zero: first kernel, plain launch
    zero_rowsum_kernel<<<node_blocks, TPB>>>();

    {   // accum (PDL-dependent on zero)
        cudaLaunchConfig_t cfg = {};
        cfg.gridDim = dim3(edge_blocks);
        cfg.blockDim = dim3(TPB);
        cfg.attrs = pdl_attr;
        cfg.numAttrs = 1;
        cudaLaunchKernelEx(&cfg, accum_kernel, row, edge_attr, E);
    }
    {   // recip (PDL-dependent on accum)
        cudaLaunchConfig_t cfg = {};
        cfg.gridDim = dim3(node_blocks);
        cfg.blockDim = dim3(TPB);
        cfg.attrs = pdl_attr;
        cfg.numAttrs = 1;
        cudaLaunchKernelEx(&cfg, recip_kernel);
    }
    {   // norm (PDL-dependent on recip)
        cudaLaunchConfig_t cfg = {};
        cfg.gridDim = dim3(edge_blocks);
        cfg.blockDim = dim3(TPB);
        cfg.attrs = pdl_attr;
        cfg.numAttrs = 1;
        cudaLaunchKernelEx(&cfg, norm_kernel, row, edge_attr, out, E);
    }
}

// round 12
// speedup vs baseline: 1.0685x; 1.0112x over previous
#include <cuda_runtime.h>
#include <cuda_bf16.h>

#define N_NODES 1000000

// 4 MB scratch for per-node exp-sums (static __device__ per allocation rules)
__device__ float g_rowsum[N_NODES];

__device__ __forceinline__ void pdl_trigger() {
    asm volatile("griddepcontrol.launch_dependents;");
}
__device__ __forceinline__ void pdl_wait() {
    asm volatile("griddepcontrol.wait;" ::: "memory");
}

__device__ __forceinline__ float et_of(float x) {
    // exp(leaky_relu(x, 0.01)) ; leaky_relu(x) == max(x, 0.01x)
    float lr = fmaxf(x, 0.01f * x);
    return __expf(lr);
}

__global__ void zero_rowsum_kernel() {
    pdl_trigger();
    int i = blockIdx.x * blockDim.x + threadIdx.x;
    if (i < N_NODES / 4) {
        reinterpret_cast<float4*>(g_rowsum)[i] = make_float4(0.f, 0.f, 0.f, 0.f);
    }
}

__global__ void accum_kernel(const int* __restrict__ row,
                             const float* __restrict__ attr,
                             int E) {
    pdl_trigger();
    long long i = (long long)(blockIdx.x * blockDim.x + threadIdx.x) * 4;
    if (i + 3 < E) {
        // independent streaming loads issue BEFORE waiting on zero_rowsum
        int4   r = *reinterpret_cast<const int4*>(row + i);
        float4 a = *reinterpret_cast<const float4*>(attr + i);
        float e0 = et_of(a.x), e1 = et_of(a.y), e2 = et_of(a.z), e3 = et_of(a.w);
        pdl_wait();
        atomicAdd(&g_rowsum[r.x], e0);
        atomicAdd(&g_rowsum[r.y], e1);
        atomicAdd(&g_rowsum[r.z], e2);
        atomicAdd(&g_rowsum[r.w], e3);
    } else {
        pdl_wait();
        for (; i < E; i++) {
            atomicAdd(&g_rowsum[row[i]], et_of(attr[i]));
        }
    }
}

__global__ void norm_kernel(const int* __restrict__ row,
                            const float* __restrict__ attr,
                            float* __restrict__ out,
                            int E) {
    long long i = (long long)(blockIdx.x * blockDim.x + threadIdx.x) * 4;
    if (i + 3 < E) {
        // streaming prologue overlaps accum_kernel's tail via PDL
        int4   r = *reinterpret_cast<const int4*>(row + i);
        float4 a = *reinterpret_cast<const float4*>(attr + i);
        float e0 = et_of(a.x), e1 = et_of(a.y), e2 = et_of(a.z), e3 = et_of(a.w);
        pdl_wait();
        float s0 = __ldg(&g_rowsum[r.x]);
        float s1 = __ldg(&g_rowsum[r.y]);
        float s2 = __ldg(&g_rowsum[r.z]);
        float s3 = __ldg(&g_rowsum[r.w]);
        float4 o;
        o.x = __fdividef(e0, s0);
        o.y = __fdividef(e1, s1);
        o.z = __fdividef(e2, s2);
        o.w = __fdividef(e3, s3);
        *reinterpret_cast<float4*>(out + i) = o;
    } else {
        pdl_wait();
        for (; i < E; i++) {
            out[i] = __fdividef(et_of(attr[i]), __ldg(&g_rowsum[row[i]]));
        }
    }
}

extern "C" void kernel_launch(void* const* d_in, const int* in_sizes, int n_in,
                              void* d_out, int out_size) {
    // metadata order: edge_index (int32, [2, E] row-major), edge_attr (f32, [E]), N
    const int*   edge_index = (const int*)d_in[0];
    const float* edge_attr  = (const float*)d_in[1];
    float*       out        = (float*)d_out;

    int E = in_sizes[1];           // edge_attr element count
    const int* row = edge_index;   // edge_index[0] = first E elements

    const unsigned TPB = 256;
    unsigned node_blocks = (N_NODES / 4 + TPB - 1) / TPB;
    unsigned edge_threads = (unsigned)((E + 3) / 4);
    unsigned edge_blocks = (edge_threads + TPB - 1) / TPB;

    cudaLaunchAttribute pdl_attr[1];
    pdl_attr[0].id = cudaLaunchAttributeProgrammaticStreamSerialization;
    pdl_attr[0].val.programmaticStreamSerializationAllowed = 1;

    // zero: first kernel, plain launch
    zero_rowsum_kernel<<<node_blocks, TPB>>>();

    {   // accum (PDL-dependent on zero)
        cudaLaunchConfig_t cfg = {};
        cfg.gridDim = dim3(edge_blocks);
        cfg.blockDim = dim3(TPB);
        cfg.attrs = pdl_attr;
        cfg.numAttrs = 1;
        cudaLaunchKernelEx(&cfg, accum_kernel, row, edge_attr, E);
    }
    {   // norm (PDL-dependent on accum)
        cudaLaunchConfig_t cfg = {};
        cfg.gridDim = dim3(edge_blocks);
        cfg.blockDim = dim3(TPB);
        cfg.attrs = pdl_attr;
        cfg.numAttrs = 1;
        cudaLaunchKernelEx(&cfg, norm_kernel, row, edge_attr, out, E);
    }
}